// round 7
// baseline (speedup 1.0000x reference)
#include <cuda_runtime.h>
#include <cstdint>
#include <cstddef>

#define NB      8
#define NPTS    16384
#define KNB     32
#define CNUM    256
#define CLEN    32
#define PBLK    128

// ----------------- global scratch -----------------
__device__ float  g_flat[(size_t)NB * NPTS * 64];   // point-major gated features
__device__ float  g_xatt[NB * NPTS];
__device__ int    g_start[2048];
__device__ float2 g_mm[2][2048];      // (m0,m1) per curve, double-buffered
__device__ float2 g_w2cp[2][2048];    // (w2.cur, w2.pre)
__device__ float  g_lk[2][2048];      // Lk per curve
__device__ double g_part[2][PBLK][9];
__device__ float  g_stage[2048 * CLEN * 64];   // [curve][step][c]
__device__ unsigned int g_barcnt;

// ----------------- K1: gate + transpose -----------------
__global__ void k_prep(const float* __restrict__ x, const float* __restrict__ attw) {
    __shared__ float sx[64][129];
    __shared__ float satt[128];
    __shared__ float swa[64];
    int t = threadIdx.x;                 // 256 threads
    int tile = blockIdx.x;               // 8 * 128
    int b = tile >> 7, p0 = (tile & 127) << 7;

    if (t < 64) swa[t] = attw[t];
    for (int i = t; i < 64 * 128; i += 256) {
        int c = i >> 7, p = i & 127;
        sx[c][p] = x[((size_t)(b * 64 + c) << 14) + p0 + p];
    }
    __syncthreads();
    if (t < 128) {
        float s = 0.f;
#pragma unroll
        for (int c = 0; c < 64; c++) s += sx[c][t] * swa[c];
        float a = 1.f / (1.f + expf(-s));
        satt[t] = a;
        g_xatt[((size_t)b << 14) + p0 + t] = a;
    }
    __syncthreads();
    for (int i = t; i < 128 * 64; i += 256) {
        int p = i >> 6, c = i & 63;
        g_flat[(((size_t)b << 14) + (size_t)(p0 + p)) * 64 + c] = sx[c][p] * satt[p];
    }
    if (tile == 0 && t == 0) g_barcnt = 0u;
}

// ----------------- K2: exact top-256 per batch (bitonic in smem) -----------------
__global__ void __launch_bounds__(1024, 1) k_topk() {
    extern __shared__ unsigned long long keys[];   // 16384 * 8B = 128 KB
    int b = blockIdx.x, t = threadIdx.x;
    for (int i = t; i < NPTS; i += 1024) {
        unsigned int fb = __float_as_uint(g_xatt[((size_t)b << 14) + i]); // positive floats
        keys[i] = ((unsigned long long)fb << 32) | (unsigned int)(0xFFFFFFFFu - (unsigned)i);
    }
    for (int size = 2; size <= NPTS; size <<= 1) {
        for (int stride = size >> 1; stride > 0; stride >>= 1) {
            __syncthreads();
            for (int i = t; i < NPTS / 2; i += 1024) {
                int pos = 2 * i - (i & (stride - 1));
                unsigned long long a = keys[pos], bb = keys[pos + stride];
                bool asc = (pos & size) != 0;                 // overall: descending
                bool sw = asc ? (a > bb) : (a < bb);
                if (sw) { keys[pos] = bb; keys[pos + stride] = a; }
            }
        }
    }
    __syncthreads();
    if (t < CNUM) {
        unsigned low = (unsigned)(keys[t] & 0xFFFFFFFFull);
        int p = (int)(0xFFFFFFFFu - low);
        g_start[(b << 8) + t] = (b << 14) + p;
    }
}

// ----------------- K3: persistent curve walk (ONE grid barrier / step) -----------------
struct SW {
    float  cur[16][64], pre[16][64];
    float  w1[64], w2[64], mw[256];
    float  lpv[16][32], Pk[16][32], Rk[16][32], Nk[16][32];
    int    pts[16][32];
    float  hpart[16][4][32];
    float  red[16][2][4];
    float  mm0[16], mm1[16], lpre[16], na[16], ga[16], gb[16];
    float  Lk[16], Qk[16];
    int    fcur[16], sel[16];
    float  ag, ab, mg0, mg1, mb0, mb1;
    float  bnf[8];
    double bns[10];
    double dwp[32][3];
};

__device__ __forceinline__ float wredsum(float v) {
#pragma unroll
    for (int o = 16; o; o >>= 1) v += __shfl_xor_sync(0xffffffffu, v, o);
    return v;
}

__device__ __forceinline__ void grid_bar() {
    __syncthreads();
    if (threadIdx.x == 0) {
        __threadfence();
        unsigned tok = atomicAdd(&g_barcnt, 1u);
        unsigned target = (tok / PBLK + 1u) * PBLK;
        unsigned v;
        do {
            asm volatile("ld.global.acquire.gpu.u32 %0, [%1];" : "=r"(v) : "l"(&g_barcnt));
        } while (v < target);
    }
    __syncthreads();
}

// gate pair for curve (b,j) given that batch's raw momentum values
__device__ __forceinline__ void gates_for(const float2* mr, int jj,
                                          float mean0, float is0, float mean1, float is1,
                                          float mg0, float mg1, float mb0, float mb1,
                                          float& gaV, float& gbV) {
    int p0 = 2 * jj, p1 = p0 + 1;
    int q0 = p0 & 255, o0 = p0 >> 8, q1 = p1 & 255, o1 = p1 >> 8;
    float2 A = mr[q0];
    float z0 = (A.x - mean0) * is0 * mg0 + mb0;
    float z1 = (A.y - mean1) * is1 * mg1 + mb1;
    float mx = fmaxf(z0, z1);
    float e0 = expf(z0 - mx), e1 = expf(z1 - mx);
    gaV = ((o0 == 0) ? e0 : e1) / (e0 + e1);
    float2 B = mr[q1];
    z0 = (B.x - mean0) * is0 * mg0 + mb0;
    z1 = (B.y - mean1) * is1 * mg1 + mb1;
    mx = fmaxf(z0, z1);
    e0 = expf(z0 - mx); e1 = expf(z1 - mx);
    gbV = ((o1 == 0) ? e0 : e1) / (e0 + e1);
}

__global__ void __launch_bounds__(1024, 1) k_walk(
    const int* __restrict__ idx,
    const float* __restrict__ agw, const float* __restrict__ agg, const float* __restrict__ agb,
    const float* __restrict__ mwi, const float* __restrict__ mgi, const float* __restrict__ mbi)
{
    __shared__ SW sm;
    extern __shared__ float dyn[];
    float*  pv  = dyn;                                  // [16][32][65]
    float4* bk4 = (float4*)(dyn + 16 * 32 * 65);        // [16][64] (w1,cur,pre,-)

    int t = threadIdx.x;
    int s = t >> 6, t64 = t & 63, half = t64 >> 5, lane = t & 31, c = t64;
    int wrp = t >> 5;
    int gi = (blockIdx.x << 4) + s;
    int b = gi >> 8, j = gi & 255, boff = b << 14;

    if (t < 64) { sm.w1[t] = agw[t]; sm.w2[t] = agw[64 + t]; }
    if (t >= 64 && t < 320) sm.mw[t - 64] = mwi[t - 64];
    if (t == 0) {
        sm.ag = agg[0]; sm.ab = agb[0];
        sm.mg0 = mgi[0]; sm.mg1 = mgi[1]; sm.mb0 = mbi[0]; sm.mb1 = mbi[1];
    }
    if (t64 == 0) sm.fcur[s] = g_start[gi];
    __syncthreads();

    for (int step = 0; step < CLEN; step++) {
        int buf = step & 1;
        // ================= phase A (pre-barrier) =================
        if (step > 0) {
            float cm = sm.cur[s][c], pm = sm.pre[s][c];
            bk4[s * 64 + c] = make_float4(sm.w1[c], cm, pm, 0.f);
            float r0 = sm.mw[c] * cm + sm.mw[64 + c] * pm;
            float r1 = sm.mw[128 + c] * cm + sm.mw[192 + c] * pm;
            float r2 = sm.w2[c] * cm;
            float r3 = sm.w2[c] * pm;
            r0 = wredsum(r0); r1 = wredsum(r1); r2 = wredsum(r2); r3 = wredsum(r3);
            if (lane == 0) {
                float* rr = sm.red[s][half];
                rr[0] = r0; rr[1] = r1; rr[2] = r2; rr[3] = r3;
            }
        } else {
            int fc = sm.fcur[s];
            float pf = g_flat[((size_t)fc << 6) + c];
            sm.pre[s][c] = pf;
            bk4[s * 64 + c] = make_float4(sm.w1[c], 0.f, 0.f, 0.f);
            float r = wredsum(sm.w2[c] * pf);
            if (lane == 0) sm.red[s][half][0] = r;
        }
        if (t64 < 32) sm.pts[s][t64] = idx[(size_t)sm.fcur[s] * KNB + t64] + boff;
        __syncthreads();
        if (t64 == 0) {
            if (step > 0) {
                float m0 = sm.red[s][0][0] + sm.red[s][1][0];
                float m1 = sm.red[s][0][1] + sm.red[s][1][1];
                sm.mm0[s] = m0; sm.mm1[s] = m1;
                g_mm[buf][gi]   = make_float2(m0, m1);
                g_w2cp[buf][gi] = make_float2(sm.red[s][0][2] + sm.red[s][1][2],
                                              sm.red[s][0][3] + sm.red[s][1][3]);
            } else {
                sm.lpre[s] = sm.red[s][0][0] + sm.red[s][1][0];
            }
        }
        // gather 32 neighbor rows (float4 loads, scalar stores to stride-65 smem)
        {
            int kk = t64 >> 4, col = (t64 & 15) << 2;
#pragma unroll
            for (int k0 = 0; k0 < 8; k0++) {
                int k = k0 * 4 + kk;
                int pt = sm.pts[s][k];
                float4 v4 = __ldg((const float4*)&g_flat[((size_t)pt << 6) + col]);
                float* dst = &pv[(s * 32 + k) * 65 + col];
                dst[0] = v4.x; dst[1] = v4.y; dst[2] = v4.z; dst[3] = v4.w;
            }
        }
        __syncthreads();

        // single per-k pass: accL, P = cur.nb, R = pre.nb, N = |nb|^2
        {
            int off = half * 32;
            const float* pvb = &pv[(s * 32 + lane) * 65 + off];
            const float4* bk = &bk4[s * 64 + off];
            float accL = 0.f, accP = 0.f, accR = 0.f, accN = 0.f;
#pragma unroll 8
            for (int cc = 0; cc < 32; cc++) {
                float v = pvb[cc];
                float4 q = bk[cc];
                accL += v * q.x;
                float nb = v - q.y;
                accP += q.y * nb;
                accR += q.z * nb;
                accN += nb * nb;
            }
            if (half == 1) {
                sm.hpart[s][0][lane] = accL;
                sm.hpart[s][1][lane] = accP;
                sm.hpart[s][2][lane] = accR;
                sm.hpart[s][3][lane] = accN;
            }
            __syncthreads();
            if (t64 < 32) {
                int k = lane;
                float L = accL + sm.hpart[s][0][k];
                sm.lpv[s][k] = L;
                sm.Pk[s][k] = accP + sm.hpart[s][1][k];
                sm.Rk[s][k] = accR + sm.hpart[s][2][k];
                sm.Nk[s][k] = accN + sm.hpart[s][3][k];
                float s1 = wredsum(L);
                float s2 = wredsum(L * L);
                if (k == 0) {
                    sm.Lk[s] = s1; sm.Qk[s] = s2;
                    g_lk[buf][gi] = s1;
                }
            }
        }
        __syncthreads();
        // publish block partials — ALWAYS 3 full warps participate in the shuffles
        if (t < 96) {
            int q = t >> 4, ss = t & 15;
            double v = 0.0; int dst = -1;
            if (step > 0) {
                float m0 = sm.mm0[ss], m1 = sm.mm1[ss];
                v = (q == 0) ? (double)m0 : (q == 1) ? (double)m1 :
                    (q == 2) ? (double)m0 * m0 : (q == 3) ? (double)m1 * m1 :
                    (q == 4) ? (double)sm.Lk[ss] : (double)sm.Qk[ss];
                dst = q;
            } else if (q < 5) {
                float lp = sm.lpre[ss];
                v = (q == 0) ? (double)sm.Lk[ss] : (q == 1) ? (double)sm.Qk[ss] :
                    (q == 2) ? (double)lp : (q == 3) ? (double)lp * lp
                                          : (double)lp * sm.Lk[ss];
                dst = 4 + q;
            }
#pragma unroll
            for (int o = 8; o; o >>= 1) v += __shfl_xor_sync(0xffffffffu, v, o, 16);
            if ((t & 15) == 0 && dst >= 0) g_part[buf][blockIdx.x][dst] = v;
        }
        grid_bar();   // ======== the ONLY grid barrier this step ========

        // ================= phase B (post-barrier) =================
        {
            int nq = (step > 0) ? 6 : 5, q0 = (step > 0) ? 0 : 4;
            if (t < 32 * nq) {
                int w = t >> 5, ll = t & 31;
                double a = g_part[buf][ll][q0 + w] + g_part[buf][ll + 32][q0 + w]
                         + g_part[buf][ll + 64][q0 + w] + g_part[buf][ll + 96][q0 + w];
#pragma unroll
                for (int o = 16; o; o >>= 1) a += __shfl_xor_sync(0xffffffffu, a, o);
                if (ll == 0) sm.bns[q0 + w] = a;
            }
        }
        __syncthreads();

        if (step > 0) {
            if (t == 0) {
                double m0 = sm.bns[0] * (1.0 / 2048.0), m1 = sm.bns[1] * (1.0 / 2048.0);
                double v0 = sm.bns[2] * (1.0 / 2048.0) - m0 * m0;
                double v1 = sm.bns[3] * (1.0 / 2048.0) - m1 * m1;
                sm.bnf[0] = (float)m0; sm.bnf[1] = (float)(1.0 / sqrt(v0 + 1e-5));
                sm.bnf[2] = (float)m1; sm.bnf[3] = (float)(1.0 / sqrt(v1 + 1e-5));
            }
            __syncthreads();
            // redundant global gates pass: 2 curves per thread, identical order in all blocks
            {
                float mean0 = sm.bnf[0], is0 = sm.bnf[1], mean1 = sm.bnf[2], is1 = sm.bnf[3];
                double a0 = 0.0, a1 = 0.0, a2 = 0.0;
#pragma unroll
                for (int r = 0; r < 2; r++) {
                    int cu = t + r * 1024;
                    int bb = cu >> 8, jj = cu & 255;
                    const float2* mr = &g_mm[buf][bb << 8];
                    float gaV, gbV;
                    gates_for(mr, jj, mean0, is0, mean1, is1,
                              sm.mg0, sm.mg1, sm.mb0, sm.mb1, gaV, gbV);
                    float2 W = g_w2cp[buf][cu];
                    float lk = g_lk[buf][cu];
                    float lp = gaV * W.x + gbV * W.y;
                    a0 += (double)lp; a1 += (double)lp * lp; a2 += (double)lp * lk;
                }
                if (t64 == 0) {   // own gates (same math as in the pass)
                    float gaV, gbV;
                    gates_for(&g_mm[buf][b << 8], j, mean0, is0, mean1, is1,
                              sm.mg0, sm.mg1, sm.mb0, sm.mb1, gaV, gbV);
                    sm.ga[s] = gaV; sm.gb[s] = gbV;
                }
#pragma unroll
                for (int o = 16; o; o >>= 1) {
                    a0 += __shfl_xor_sync(0xffffffffu, a0, o);
                    a1 += __shfl_xor_sync(0xffffffffu, a1, o);
                    a2 += __shfl_xor_sync(0xffffffffu, a2, o);
                }
                if (lane == 0) { sm.dwp[wrp][0] = a0; sm.dwp[wrp][1] = a1; sm.dwp[wrp][2] = a2; }
            }
            __syncthreads();
            if (t < 32) {
                double v0 = sm.dwp[t][0], v1 = sm.dwp[t][1], v2 = sm.dwp[t][2];
#pragma unroll
                for (int o = 16; o; o >>= 1) {
                    v0 += __shfl_xor_sync(0xffffffffu, v0, o);
                    v1 += __shfl_xor_sync(0xffffffffu, v1, o);
                    v2 += __shfl_xor_sync(0xffffffffu, v2, o);
                }
                if (t == 0) { sm.bns[6] = v0; sm.bns[7] = v1; sm.bns[8] = v2; }
            }
            // pre update + na + own lpre (elementwise, bitwise as before)
            {
                float cu = sm.cur[s][c], po = sm.pre[s][c];
                float pnew = sm.ga[s] * cu + sm.gb[s] * po;
                sm.pre[s][c] = pnew;
                float ac = cu - pnew;
                float r0 = wredsum(ac * ac);
                float r1 = wredsum(sm.w2[c] * pnew);
                if (lane == 0) { sm.red[s][half][0] = r0; sm.red[s][half][1] = r1; }
            }
            __syncthreads();
            if (t64 == 0) {
                sm.na[s]   = sqrtf(sm.red[s][0][0] + sm.red[s][1][0]);
                sm.lpre[s] = sm.red[s][0][1] + sm.red[s][1][1];
            }
        }
        __syncthreads();
        if (t == 0) {
            double S  = sm.bns[4] + 32.0 * sm.bns[6];
            double SS = sm.bns[5] + 2.0 * sm.bns[8] + 32.0 * sm.bns[7];
            double mean = S * (1.0 / 65536.0);
            double var  = SS * (1.0 / 65536.0) - mean * mean;
            sm.bnf[4] = (float)mean;
            sm.bnf[5] = (float)sqrt(var + 1e-5);
        }
        __syncthreads();

        // ================= phase C: agent BN + crossover + select =================
        if (t64 < 32) {
            int k = t64;
            float lg = sm.lpv[s][k] + sm.lpre[s];
            float z = (lg - sm.bnf[4]) / sm.bnf[5] * sm.ag + sm.ab;
            float l2 = z;
            if (step > 0) {
                float oma = 1.f - sm.ga[s];
                float dotv = oma * sm.Pk[s][k] - sm.gb[s] * sm.Rk[s][k];
                float nbl = sqrtf(sm.Nk[s][k]);
                float div = fmaxf(sm.na[s] * nbl, 1e-8f);
                float d = 1.f + dotv / div;
                d = fminf(fmaxf(d, 0.f), 1.f);
                l2 = z * d;
            }
            float mx = l2;
#pragma unroll
            for (int o = 16; o; o >>= 1) mx = fmaxf(mx, __shfl_xor_sync(0xffffffffu, mx, o));
            float e = expf(l2 - mx);
            float se = wredsum(e);
            float y = e / se;
            unsigned long long key =
                ((unsigned long long)__float_as_uint(y) << 32) | (unsigned)(31 - k);
#pragma unroll
            for (int o = 16; o; o >>= 1) {
                unsigned long long kk = __shfl_xor_sync(0xffffffffu, key, o);
                if (kk > key) key = kk;
            }
            if (k == 0) {
                int sl = 31 - (int)(key & 0xFFFFFFFFull);
                sm.sel[s] = sl;
                sm.fcur[s] = sm.pts[s][sl];
            }
        }
        __syncthreads();
        {
            float nc = pv[(s * 32 + sm.sel[s]) * 65 + c];
            sm.cur[s][c] = nc;
            g_stage[((size_t)gi * CLEN + step) * 64 + c] = nc;   // coalesced
        }
        __syncthreads();
    }
}

// ----------------- K4: stage -> out transpose -----------------
__global__ void k_out(float* __restrict__ out) {
    __shared__ float tile[CLEN][65];
    int gi = blockIdx.x, b = gi >> 8, j = gi & 255;
    int t = threadIdx.x;   // 256
    for (int i = t; i < CLEN * 64; i += 256) {
        int st = i >> 6, c = i & 63;
        tile[st][c] = g_stage[((size_t)gi * CLEN + st) * 64 + c];
    }
    __syncthreads();
    for (int i = t; i < 64 * CLEN; i += 256) {
        int c = i >> 5, st = i & 31;
        out[((size_t)(b * 64 + c) * 256 + (size_t)j) * CLEN + st] = tile[st][c];
    }
}

// ----------------- launch -----------------
extern "C" void kernel_launch(void* const* d_in, const int* in_sizes, int n_in,
                              void* d_out, int out_size) {
    const float* x    = (const float*)d_in[0];
    // d_in[1] = xyz (unused by the reference forward)
    const int*   idx  = (const int*)d_in[2];
    const float* attw = (const float*)d_in[3];
    const float* agw  = (const float*)d_in[4];
    const float* agg  = (const float*)d_in[5];
    const float* agb  = (const float*)d_in[6];
    const float* mw   = (const float*)d_in[7];
    const float* mg   = (const float*)d_in[8];
    const float* mb   = (const float*)d_in[9];
    float* out = (float*)d_out;

    const int WALK_DYN = (16 * 32 * 65) * 4 + 16 * 64 * 16;   // pv + bk4
    cudaFuncSetAttribute(k_topk, cudaFuncAttributeMaxDynamicSharedMemorySize,
                         NPTS * sizeof(unsigned long long));
    cudaFuncSetAttribute(k_walk, cudaFuncAttributeMaxDynamicSharedMemorySize, WALK_DYN);

    k_prep<<<NB * 128, 256>>>(x, attw);
    k_topk<<<NB, 1024, NPTS * sizeof(unsigned long long)>>>();
    k_walk<<<PBLK, 1024, WALK_DYN>>>(idx, agw, agg, agb, mw, mg, mb);
    k_out<<<2048, 256>>>(out);
}

// round 8
// speedup vs baseline: 1.0671x; 1.0671x over previous
#include <cuda_runtime.h>
#include <cstdint>
#include <cstddef>

#define NB      8
#define NPTS    16384
#define KNB     32
#define CLEN    32

// ----------------- global scratch -----------------
__device__ float  g_flat[(size_t)NB * NPTS * 64];   // point-major gated features
__device__ float  g_xatt[NB * NPTS];
__device__ int    g_start[2048];
__device__ float  g_cur[2048][64];
__device__ float  g_pre[2048][64];
__device__ int    g_fcur[2048];
__device__ float2 g_mm[2048];       // (m0,m1) per curve
__device__ float2 g_w2cp[2048];     // (w2.cur, w2.pre)
__device__ float  g_lkv[2048];      // Lk per curve
__device__ float  g_lpre[2048];
__device__ float2 g_gates[2048];
__device__ float  g_Lv[2048 * 32];
__device__ float  g_Pv[2048 * 32];
__device__ float  g_Rv[2048 * 32];
__device__ float  g_Nv[2048 * 32];
__device__ int    g_pts[2048 * 32];
__device__ double g_partA[128][6];
__device__ double g_partB[16][3];
__device__ double g_tot2[2];        // total sum(Lk), sum(Qk)
__device__ float  g_stage[(size_t)2048 * CLEN * 64];

__device__ __forceinline__ float wredsum(float v) {
#pragma unroll
    for (int o = 16; o; o >>= 1) v += __shfl_xor_sync(0xffffffffu, v, o);
    return v;
}

// gate pair for curve (b,j) given that batch's raw momentum values
__device__ __forceinline__ void gates_for(const float2* mr, int jj,
                                          float mean0, float is0, float mean1, float is1,
                                          float mg0, float mg1, float mb0, float mb1,
                                          float& gaV, float& gbV) {
    int p0 = 2 * jj, p1 = p0 + 1;
    int q0 = p0 & 255, o0 = p0 >> 8, q1 = p1 & 255, o1 = p1 >> 8;
    float2 A = mr[q0];
    float z0 = (A.x - mean0) * is0 * mg0 + mb0;
    float z1 = (A.y - mean1) * is1 * mg1 + mb1;
    float mx = fmaxf(z0, z1);
    float e0 = expf(z0 - mx), e1 = expf(z1 - mx);
    gaV = ((o0 == 0) ? e0 : e1) / (e0 + e1);
    float2 B = mr[q1];
    z0 = (B.x - mean0) * is0 * mg0 + mb0;
    z1 = (B.y - mean1) * is1 * mg1 + mb1;
    mx = fmaxf(z0, z1);
    e0 = expf(z0 - mx); e1 = expf(z1 - mx);
    gbV = ((o1 == 0) ? e0 : e1) / (e0 + e1);
}

// ----------------- K1: gate + transpose -----------------
__global__ void k_prep(const float* __restrict__ x, const float* __restrict__ attw) {
    __shared__ float sx[64][129];
    __shared__ float satt[128];
    __shared__ float swa[64];
    int t = threadIdx.x;                 // 256 threads
    int tile = blockIdx.x;               // 8 * 128
    int b = tile >> 7, p0 = (tile & 127) << 7;

    if (t < 64) swa[t] = attw[t];
    for (int i = t; i < 64 * 128; i += 256) {
        int c = i >> 7, p = i & 127;
        sx[c][p] = x[((size_t)(b * 64 + c) << 14) + p0 + p];
    }
    __syncthreads();
    if (t < 128) {
        float s = 0.f;
#pragma unroll
        for (int c = 0; c < 64; c++) s += sx[c][t] * swa[c];
        float a = 1.f / (1.f + expf(-s));
        satt[t] = a;
        g_xatt[((size_t)b << 14) + p0 + t] = a;
    }
    __syncthreads();
    for (int i = t; i < 128 * 64; i += 256) {
        int p = i >> 6, c = i & 63;
        g_flat[(((size_t)b << 14) + (size_t)(p0 + p)) * 64 + c] = sx[c][p] * satt[p];
    }
}

// ----------------- K2: exact top-256 via histogram threshold + small bitonic -----------------
__global__ void __launch_bounds__(1024, 1) k_topk() {
    __shared__ int hist[2048];
    __shared__ unsigned long long cand[4096];
    __shared__ int csum[32];
    __shared__ int s_cnt, s_B;
    int b = blockIdx.x, t = threadIdx.x;
    int w = t >> 5, lane = t & 31;

    for (int i = t; i < 2048; i += 1024) hist[i] = 0;
    if (t == 0) s_cnt = 0;
    __syncthreads();
    for (int i = t; i < NPTS; i += 1024) {
        unsigned u = __float_as_uint(g_xatt[((size_t)b << 14) + i]);  // (0,1] positive
        atomicAdd(&hist[u >> 19], 1);
    }
    __syncthreads();
    // chunk sums: warp w sums hist[w*64 .. w*64+63]
    {
        int acc = 0;
        for (int i = lane; i < 64; i += 32) acc += hist[w * 64 + i];
#pragma unroll
        for (int o = 16; o; o >>= 1) acc += __shfl_xor_sync(0xffffffffu, acc, o);
        if (lane == 0) csum[w] = acc;
    }
    __syncthreads();
    if (t == 0) {
        int accum = 0, wsel = 0;
        for (int ww = 31; ww >= 0; ww--) {
            if (accum + csum[ww] >= 256) { wsel = ww; break; }
            accum += csum[ww];
        }
        int B = wsel * 64;
        for (int bkt = wsel * 64 + 63; bkt >= wsel * 64; bkt--) {
            accum += hist[bkt];
            if (accum >= 256) { B = bkt; break; }
        }
        s_B = B;
    }
    __syncthreads();
    int B = s_B;
    for (int i = t; i < NPTS; i += 1024) {
        unsigned u = __float_as_uint(g_xatt[((size_t)b << 14) + i]);
        if ((int)(u >> 19) >= B) {
            int p = atomicAdd(&s_cnt, 1);
            if (p < 4096)
                cand[p] = ((unsigned long long)u << 32) | (unsigned)(0xFFFFFFFFu - (unsigned)i);
        }
    }
    __syncthreads();
    int n = s_cnt; if (n > 4096) n = 4096;
    for (int i = t; i < 4096; i += 1024)
        if (i >= n) cand[i] = 0ull;          // pads sort last (real keys > 0)
    // bitonic sort descending, 4096 keys
    for (int size = 2; size <= 4096; size <<= 1) {
        for (int stride = size >> 1; stride > 0; stride >>= 1) {
            __syncthreads();
            for (int i = t; i < 2048; i += 1024) {
                int pos = 2 * i - (i & (stride - 1));
                unsigned long long a = cand[pos], bb = cand[pos + stride];
                bool asc = (pos & size) != 0;
                bool sw = asc ? (a > bb) : (a < bb);
                if (sw) { cand[pos] = bb; cand[pos + stride] = a; }
            }
        }
    }
    __syncthreads();
    if (t < 256) {
        unsigned low = (unsigned)(cand[t] & 0xFFFFFFFFull);
        int p = (int)(0xFFFFFFFFu - low);
        g_start[(b << 8) + t] = (b << 14) + p;
    }
}

// ----------------- per-step kernel A: momentum dots + gather + per-k dots -----------------
struct SWA {
    float w1[64], w2[64], mw[256];
    int   pts[16][32];
    int   sfc[16];
    float red[16][2][4];
    float mm0[16], mm1[16], sLk[16], sQk[16];
    float hpart[16][4][32];
};

__global__ void __launch_bounds__(1024, 1) k_A(int step, const int* __restrict__ idx,
        const float* __restrict__ agw, const float* __restrict__ mwi)
{
    __shared__ SWA sm;
    extern __shared__ float dyn[];
    float*  pv  = dyn;                                  // [16][32][65]
    float4* bk4 = (float4*)(dyn + 16 * 32 * 65);        // [16][64] (w1,cur,pre,-)

    int t = threadIdx.x;
    int s = t >> 6, t64 = t & 63, half = t64 >> 5, lane = t & 31, c = t64;
    int gi = (blockIdx.x << 4) + s;
    int boff = (gi >> 8) << 14;

    if (t < 64) { sm.w1[t] = agw[t]; sm.w2[t] = agw[64 + t]; }
    if (t >= 256 && t < 512) sm.mw[t - 256] = mwi[t - 256];
    if (t64 == 0) sm.sfc[s] = (step == 0) ? g_start[gi] : g_fcur[gi];
    __syncthreads();
    int fc = sm.sfc[s];

    float cu, pm;
    if (step == 0) {
        pm = g_flat[((size_t)fc << 6) + c];
        cu = 0.f;
        g_pre[gi][c] = pm;
    } else {
        cu = g_cur[gi][c];
        pm = g_pre[gi][c];
    }
    bk4[s * 64 + c] = make_float4(sm.w1[c], cu, pm, 0.f);
    {   // momentum raw + w2 dots (cu=0 at step 0 makes these exactly what we need)
        float r0 = sm.mw[c] * cu + sm.mw[64 + c] * pm;
        float r1 = sm.mw[128 + c] * cu + sm.mw[192 + c] * pm;
        float r2 = sm.w2[c] * cu;
        float r3 = sm.w2[c] * pm;
        r0 = wredsum(r0); r1 = wredsum(r1); r2 = wredsum(r2); r3 = wredsum(r3);
        if (lane == 0) {
            float* rr = sm.red[s][half];
            rr[0] = r0; rr[1] = r1; rr[2] = r2; rr[3] = r3;
        }
    }
    if (t64 < 32) sm.pts[s][t64] = idx[(size_t)fc * KNB + t64] + boff;
    __syncthreads();
    if (t64 == 0) {
        float m0 = sm.red[s][0][0] + sm.red[s][1][0];
        float m1 = sm.red[s][0][1] + sm.red[s][1][1];
        sm.mm0[s] = m0; sm.mm1[s] = m1;
        g_mm[gi]   = make_float2(m0, m1);
        g_w2cp[gi] = make_float2(sm.red[s][0][2] + sm.red[s][1][2],
                                 sm.red[s][0][3] + sm.red[s][1][3]);
    }
    // gather 32 neighbor rows (float4 loads)
    {
        int kk = t64 >> 4, col = (t64 & 15) << 2;
#pragma unroll
        for (int k0 = 0; k0 < 8; k0++) {
            int k = k0 * 4 + kk;
            int pt = sm.pts[s][k];
            float4 v4 = __ldg((const float4*)&g_flat[((size_t)pt << 6) + col]);
            float* dst = &pv[(s * 32 + k) * 65 + col];
            dst[0] = v4.x; dst[1] = v4.y; dst[2] = v4.z; dst[3] = v4.w;
        }
    }
    __syncthreads();
    // per-k pass: L = w1.pv, P = cur.nb, R = pre.nb, N = |nb|^2 (nb elementwise!)
    {
        int off = half * 32;
        const float* pvb = &pv[(s * 32 + lane) * 65 + off];
        const float4* bk = &bk4[s * 64 + off];
        float accL = 0.f, accP = 0.f, accR = 0.f, accN = 0.f;
#pragma unroll 8
        for (int cc = 0; cc < 32; cc++) {
            float v = pvb[cc];
            float4 q = bk[cc];
            accL += v * q.x;
            float nb = v - q.y;
            accP += q.y * nb;
            accR += q.z * nb;
            accN += nb * nb;
        }
        if (half == 1) {
            sm.hpart[s][0][lane] = accL;
            sm.hpart[s][1][lane] = accP;
            sm.hpart[s][2][lane] = accR;
            sm.hpart[s][3][lane] = accN;
        }
        __syncthreads();
        if (t64 < 32) {
            int k = lane, base = gi * 32 + k;
            float L = accL + sm.hpart[s][0][k];
            g_Lv[base] = L;
            g_Pv[base] = accP + sm.hpart[s][1][k];
            g_Rv[base] = accR + sm.hpart[s][2][k];
            g_Nv[base] = accN + sm.hpart[s][3][k];
            g_pts[base] = sm.pts[s][k];
            float s1 = wredsum(L);
            float s2 = wredsum(L * L);
            if (k == 0) {
                sm.sLk[s] = s1; sm.sQk[s] = s2;
                g_lkv[gi] = s1;
            }
        }
    }
    __syncthreads();
    // publish block partials (3 full warps, width-16 groups)
    if (t < 96) {
        int q = t >> 4, ss = t & 15;
        float m0 = sm.mm0[ss], m1 = sm.mm1[ss];
        double v = (q == 0) ? (double)m0 : (q == 1) ? (double)m1 :
                   (q == 2) ? (double)m0 * m0 : (q == 3) ? (double)m1 * m1 :
                   (q == 4) ? (double)sm.sLk[ss] : (double)sm.sQk[ss];
#pragma unroll
        for (int o = 8; o; o >>= 1) v += __shfl_xor_sync(0xffffffffu, v, o, 16);
        if ((t & 15) == 0) g_partA[blockIdx.x][q] = v;
    }
}

// ----------------- per-step kernel B: momentum BN + gates + lpre partials -----------------
__global__ void __launch_bounds__(128, 1) k_B(int step,
        const float* __restrict__ mgi, const float* __restrict__ mbi)
{
    __shared__ double sred[128];
    __shared__ double tot[6];
    __shared__ double s0[128], s1[128], s2[128];
    int t = threadIdx.x;
    int cu_i = blockIdx.x * 128 + t;
    int b = cu_i >> 8, j = cu_i & 255;

    for (int q = 0; q < 6; q++) {
        sred[t] = g_partA[t][q];
        __syncthreads();
        for (int sft = 64; sft; sft >>= 1) {
            if (t < sft) sred[t] += sred[t + sft];
            __syncthreads();
        }
        if (t == 0) tot[q] = sred[0];
        __syncthreads();
    }

    float ga, gb;
    if (step > 0) {
        double m0 = tot[0] * (1.0 / 2048.0), m1 = tot[1] * (1.0 / 2048.0);
        double v0 = tot[2] * (1.0 / 2048.0) - m0 * m0;
        double v1 = tot[3] * (1.0 / 2048.0) - m1 * m1;
        float mean0 = (float)m0, is0 = (float)(1.0 / sqrt(v0 + 1e-5));
        float mean1 = (float)m1, is1 = (float)(1.0 / sqrt(v1 + 1e-5));
        gates_for(&g_mm[b << 8], j, mean0, is0, mean1, is1,
                  mgi[0], mgi[1], mbi[0], mbi[1], ga, gb);
    } else {
        ga = 0.f; gb = 1.f;   // lpre = w2.pre exactly at step 0
    }
    float2 W = g_w2cp[cu_i];
    float lp = ga * W.x + gb * W.y;
    g_gates[cu_i] = make_float2(ga, gb);
    g_lpre[cu_i] = lp;
    float lk = g_lkv[cu_i];

    s0[t] = (double)lp; s1[t] = (double)lp * lp; s2[t] = (double)lp * lk;
    __syncthreads();
    for (int sft = 64; sft; sft >>= 1) {
        if (t < sft) { s0[t] += s0[t + sft]; s1[t] += s1[t + sft]; s2[t] += s2[t + sft]; }
        __syncthreads();
    }
    if (t == 0) {
        g_partB[blockIdx.x][0] = s0[0];
        g_partB[blockIdx.x][1] = s1[0];
        g_partB[blockIdx.x][2] = s2[0];
        if (blockIdx.x == 0) { g_tot2[0] = tot[4]; g_tot2[1] = tot[5]; }
    }
}

// ----------------- per-step kernel C: agent BN + crossover + select + state update -----------------
struct SWC {
    float sga[16], sgb[16], slp[16], sna[16];
    int   sfc[16], ssel[16];
    float red[16][2];
    float bnf[2];
    float ag, ab;
};

__global__ void __launch_bounds__(1024, 1) k_C(int step,
        const float* __restrict__ agg, const float* __restrict__ agb)
{
    __shared__ SWC sm;
    int t = threadIdx.x;
    int s = t >> 6, t64 = t & 63, half = t64 >> 5, lane = t & 31, c = t64;
    int gi = (blockIdx.x << 4) + s;

    if (t < 32) {
        double v0 = 0.0, v1 = 0.0, v2 = 0.0;
        if (lane < 16) {
            v0 = g_partB[lane][0]; v1 = g_partB[lane][1]; v2 = g_partB[lane][2];
        }
#pragma unroll
        for (int o = 16; o; o >>= 1) {
            v0 += __shfl_xor_sync(0xffffffffu, v0, o);
            v1 += __shfl_xor_sync(0xffffffffu, v1, o);
            v2 += __shfl_xor_sync(0xffffffffu, v2, o);
        }
        if (lane == 0) {
            double S  = g_tot2[0] + 32.0 * v0;
            double SS = g_tot2[1] + 2.0 * v2 + 32.0 * v1;
            double mean = S * (1.0 / 65536.0);
            double var  = SS * (1.0 / 65536.0) - mean * mean;
            sm.bnf[0] = (float)mean;
            sm.bnf[1] = (float)sqrt(var + 1e-5);
            sm.ag = agg[0]; sm.ab = agb[0];
        }
    }
    if (t64 == 0) {
        float2 g = g_gates[gi];
        sm.sga[s] = g.x; sm.sgb[s] = g.y;
        sm.slp[s] = g_lpre[gi];
    }
    __syncthreads();

    float cu = g_cur[gi][c], po = g_pre[gi][c];
    float pnew = (step == 0) ? po : (sm.sga[s] * cu + sm.sgb[s] * po);
    g_pre[gi][c] = pnew;
    if (step > 0) {
        float a = cu - pnew;
        float r = wredsum(a * a);
        if (lane == 0) sm.red[s][half] = r;
    }
    __syncthreads();
    if (step > 0 && t64 == 0) sm.sna[s] = sqrtf(sm.red[s][0] + sm.red[s][1]);
    __syncthreads();

    if (t64 < 32) {
        int k = t64, base = gi * 32 + k;
        float L = g_Lv[base];
        float z = (L + sm.slp[s] - sm.bnf[0]) / sm.bnf[1] * sm.ag + sm.ab;
        float l2 = z;
        if (step > 0) {
            float P = g_Pv[base], R = g_Rv[base], N = g_Nv[base];
            float dotv = (1.f - sm.sga[s]) * P - sm.sgb[s] * R;
            float nbl = sqrtf(N);
            float dv = fmaxf(sm.sna[s] * nbl, 1e-8f);
            float d = 1.f + dotv / dv;
            d = fminf(fmaxf(d, 0.f), 1.f);
            l2 = z * d;
        }
        float mx = l2;
#pragma unroll
        for (int o = 16; o; o >>= 1) mx = fmaxf(mx, __shfl_xor_sync(0xffffffffu, mx, o));
        float e = expf(l2 - mx);
        float se = wredsum(e);
        float y = e / se;
        unsigned long long key =
            ((unsigned long long)__float_as_uint(y) << 32) | (unsigned)(31 - k);
#pragma unroll
        for (int o = 16; o; o >>= 1) {
            unsigned long long kk = __shfl_xor_sync(0xffffffffu, key, o);
            if (kk > key) key = kk;
        }
        if (k == 0) {
            int sl = 31 - (int)(key & 0xFFFFFFFFull);
            int fc2 = g_pts[gi * 32 + sl];
            sm.ssel[s] = sl;
            sm.sfc[s] = fc2;
            g_fcur[gi] = fc2;
        }
    }
    __syncthreads();
    {
        int fc = sm.sfc[s];
        float nc = g_flat[((size_t)fc << 6) + c];
        g_cur[gi][c] = nc;
        g_stage[((size_t)gi * CLEN + step) * 64 + c] = nc;
    }
}

// ----------------- K4: stage -> out transpose -----------------
__global__ void k_out(float* __restrict__ out) {
    __shared__ float tile[CLEN][65];
    int gi = blockIdx.x, b = gi >> 8, j = gi & 255;
    int t = threadIdx.x;   // 256
    for (int i = t; i < CLEN * 64; i += 256) {
        int st = i >> 6, c = i & 63;
        tile[st][c] = g_stage[((size_t)gi * CLEN + st) * 64 + c];
    }
    __syncthreads();
    for (int i = t; i < 64 * CLEN; i += 256) {
        int c = i >> 5, st = i & 31;
        out[((size_t)(b * 64 + c) * 256 + (size_t)j) * CLEN + st] = tile[st][c];
    }
}

// ----------------- launch -----------------
extern "C" void kernel_launch(void* const* d_in, const int* in_sizes, int n_in,
                              void* d_out, int out_size) {
    const float* x    = (const float*)d_in[0];
    // d_in[1] = xyz (unused by the reference forward)
    const int*   idx  = (const int*)d_in[2];
    const float* attw = (const float*)d_in[3];
    const float* agw  = (const float*)d_in[4];
    const float* agg  = (const float*)d_in[5];
    const float* agb  = (const float*)d_in[6];
    const float* mw   = (const float*)d_in[7];
    const float* mg   = (const float*)d_in[8];
    const float* mb   = (const float*)d_in[9];
    float* out = (float*)d_out;

    const int WALK_DYN = (16 * 32 * 65) * 4 + 16 * 64 * 16;   // pv + bk4
    cudaFuncSetAttribute(k_A, cudaFuncAttributeMaxDynamicSharedMemorySize, WALK_DYN);

    k_prep<<<NB * 128, 256>>>(x, attw);
    k_topk<<<NB, 1024>>>();
    for (int st = 0; st < CLEN; st++) {
        k_A<<<128, 1024, WALK_DYN>>>(st, idx, agw, mw);
        k_B<<<16, 128>>>(st, mg, mb);
        k_C<<<128, 1024>>>(st, agg, agb);
    }
    k_out<<<2048, 256>>>(out);
}

// round 10
// speedup vs baseline: 1.5477x; 1.4504x over previous
#include <cuda_runtime.h>
#include <cstdint>
#include <cstddef>

#define NB      8
#define NPTS    16384
#define KNB     32
#define CLEN    32
#define PBLK    128

// ----------------- global scratch -----------------
__device__ float  g_flat[(size_t)NB * NPTS * 64];   // point-major gated features
__device__ float  g_xatt[NB * NPTS];
__device__ int    g_start[2048];
__device__ float2 g_mm[2048];       // (m0,m1) per curve (phaseA write / phaseB read, sep by bar2)
__device__ double g_part[PBLK][6];
__device__ double g_part2[PBLK][3];
__device__ float  g_stage[(size_t)2048 * CLEN * 64];
__device__ unsigned int g_barcnt;

__device__ __forceinline__ float wredsum(float v) {
#pragma unroll
    for (int o = 16; o; o >>= 1) v += __shfl_xor_sync(0xffffffffu, v, o);
    return v;
}

__device__ __forceinline__ void grid_bar() {
    __syncthreads();
    if (threadIdx.x == 0) {
        __threadfence();
        unsigned tok = atomicAdd(&g_barcnt, 1u);
        unsigned target = (tok / PBLK + 1u) * PBLK;
        unsigned v;
        do {
            asm volatile("ld.global.acquire.gpu.u32 %0, [%1];" : "=r"(v) : "l"(&g_barcnt));
        } while (v < target);
        __threadfence();
    }
    __syncthreads();
}

// gate pair for curve (b,j) given that batch's raw momentum values
__device__ __forceinline__ void gates_for(const float2* mr, int jj,
                                          float mean0, float is0, float mean1, float is1,
                                          float mg0, float mg1, float mb0, float mb1,
                                          float& gaV, float& gbV) {
    int p0 = 2 * jj, p1 = p0 + 1;
    int q0 = p0 & 255, o0 = p0 >> 8, q1 = p1 & 255, o1 = p1 >> 8;
    float2 A = mr[q0];
    float z0 = (A.x - mean0) * is0 * mg0 + mb0;
    float z1 = (A.y - mean1) * is1 * mg1 + mb1;
    float mx = fmaxf(z0, z1);
    float e0 = expf(z0 - mx), e1 = expf(z1 - mx);
    gaV = ((o0 == 0) ? e0 : e1) / (e0 + e1);
    float2 B = mr[q1];
    z0 = (B.x - mean0) * is0 * mg0 + mb0;
    z1 = (B.y - mean1) * is1 * mg1 + mb1;
    mx = fmaxf(z0, z1);
    e0 = expf(z0 - mx); e1 = expf(z1 - mx);
    gbV = ((o1 == 0) ? e0 : e1) / (e0 + e1);
}

// ----------------- K1: gate + transpose -----------------
__global__ void k_prep(const float* __restrict__ x, const float* __restrict__ attw) {
    __shared__ float sx[64][129];
    __shared__ float satt[128];
    __shared__ float swa[64];
    int t = threadIdx.x;                 // 256 threads
    int tile = blockIdx.x;               // 8 * 128
    int b = tile >> 7, p0 = (tile & 127) << 7;

    if (t < 64) swa[t] = attw[t];
    for (int i = t; i < 64 * 128; i += 256) {
        int c = i >> 7, p = i & 127;
        sx[c][p] = x[((size_t)(b * 64 + c) << 14) + p0 + p];
    }
    __syncthreads();
    if (t < 128) {
        float s = 0.f;
#pragma unroll
        for (int c = 0; c < 64; c++) s += sx[c][t] * swa[c];
        float a = 1.f / (1.f + expf(-s));
        satt[t] = a;
        g_xatt[((size_t)b << 14) + p0 + t] = a;
    }
    __syncthreads();
    for (int i = t; i < 128 * 64; i += 256) {
        int p = i >> 6, c = i & 63;
        g_flat[(((size_t)b << 14) + (size_t)(p0 + p)) * 64 + c] = sx[c][p] * satt[p];
    }
    if (tile == 0 && t == 0) g_barcnt = 0u;
}

// ----------------- K2: exact top-256 via histogram threshold + small bitonic -----------------
__global__ void __launch_bounds__(1024, 1) k_topk() {
    __shared__ int hist[2048];
    __shared__ unsigned long long cand[4096];
    __shared__ int csum[32];
    __shared__ int s_cnt, s_B;
    int b = blockIdx.x, t = threadIdx.x;
    int w = t >> 5, lane = t & 31;

    for (int i = t; i < 2048; i += 1024) hist[i] = 0;
    if (t == 0) s_cnt = 0;
    __syncthreads();
    for (int i = t; i < NPTS; i += 1024) {
        unsigned u = __float_as_uint(g_xatt[((size_t)b << 14) + i]);  // (0,1] positive
        atomicAdd(&hist[u >> 19], 1);
    }
    __syncthreads();
    {
        int acc = 0;
        for (int i = lane; i < 64; i += 32) acc += hist[w * 64 + i];
#pragma unroll
        for (int o = 16; o; o >>= 1) acc += __shfl_xor_sync(0xffffffffu, acc, o);
        if (lane == 0) csum[w] = acc;
    }
    __syncthreads();
    if (t == 0) {
        int accum = 0, wsel = 0;
        for (int ww = 31; ww >= 0; ww--) {
            if (accum + csum[ww] >= 256) { wsel = ww; break; }
            accum += csum[ww];
        }
        int B = wsel * 64;
        for (int bkt = wsel * 64 + 63; bkt >= wsel * 64; bkt--) {
            accum += hist[bkt];
            if (accum >= 256) { B = bkt; break; }
        }
        s_B = B;
    }
    __syncthreads();
    int B = s_B;
    for (int i = t; i < NPTS; i += 1024) {
        unsigned u = __float_as_uint(g_xatt[((size_t)b << 14) + i]);
        if ((int)(u >> 19) >= B) {
            int p = atomicAdd(&s_cnt, 1);
            if (p < 4096)
                cand[p] = ((unsigned long long)u << 32) | (unsigned)(0xFFFFFFFFu - (unsigned)i);
        }
    }
    __syncthreads();
    int n = s_cnt; if (n > 4096) n = 4096;
    for (int i = t; i < 4096; i += 1024)
        if (i >= n) cand[i] = 0ull;
    for (int size = 2; size <= 4096; size <<= 1) {
        for (int stride = size >> 1; stride > 0; stride >>= 1) {
            __syncthreads();
            for (int i = t; i < 2048; i += 1024) {
                int pos = 2 * i - (i & (stride - 1));
                unsigned long long a = cand[pos], bb = cand[pos + stride];
                bool asc = (pos & size) != 0;
                bool sw = asc ? (a > bb) : (a < bb);
                if (sw) { cand[pos] = bb; cand[pos + stride] = a; }
            }
        }
    }
    __syncthreads();
    if (t < 256) {
        unsigned low = (unsigned)(cand[t] & 0xFFFFFFFFull);
        int p = (int)(0xFFFFFFFFu - low);
        g_start[(b << 8) + t] = (b << 14) + p;
    }
}

// ----------------- K3: persistent curve walk, 2 light barriers/step -----------------
struct SW {
    float  cur[16][64], pre[16][64];
    float  w1[64], w2[64], mw[256];
    float  lpv[16][32], Pk[16][32], Rk[16][32], Nk[16][32];
    int    pts[16][32];
    float  hpart[16][4][32];
    float  red[16][2][4];
    float  mm0[16], mm1[16], w2c[16], w2p[16];
    float  lpre[16], na[16], ga[16], gb[16];
    float  Lk[16], Qk[16];
    int    fcur[16], sel[16];
    float  ag, ab, mg0, mg1, mb0, mb1;
    float  bnf[8];
    double bns[6], bns2[3];
};

__global__ void __launch_bounds__(1024, 1) k_walk(
    const int* __restrict__ idx,
    const float* __restrict__ agw, const float* __restrict__ agg, const float* __restrict__ agb,
    const float* __restrict__ mwi, const float* __restrict__ mgi, const float* __restrict__ mbi)
{
    __shared__ SW sm;
    extern __shared__ float dyn[];
    float*  pv  = dyn;                                  // [16][32][65]
    float4* bk4 = (float4*)(dyn + 16 * 32 * 65);        // [16][64] (w1,cur,pre,-)

    int t = threadIdx.x;
    int s = t >> 6, t64 = t & 63, half = t64 >> 5, lane = t & 31, c = t64;
    int gi = (blockIdx.x << 4) + s;
    int b = gi >> 8, j = gi & 255, boff = b << 14;

    if (t < 64) { sm.w1[t] = agw[t]; sm.w2[t] = agw[64 + t]; }
    if (t >= 256 && t < 512) sm.mw[t - 256] = mwi[t - 256];
    if (t == 0) {
        sm.ag = agg[0]; sm.ab = agb[0];
        sm.mg0 = mgi[0]; sm.mg1 = mgi[1]; sm.mb0 = mbi[0]; sm.mb1 = mbi[1];
    }
    if (t64 == 0) sm.fcur[s] = g_start[gi];
    __syncthreads();

    for (int step = 0; step < CLEN; step++) {
        // ================= phase A (pre-bar1): all heavy, gate-independent work =================
        int fc = sm.fcur[s];
        float cu, pm;
        if (step == 0) {
            pm = g_flat[((size_t)fc << 6) + c];
            cu = 0.f;
            sm.cur[s][c] = 0.f;
            sm.pre[s][c] = pm;
        } else {
            cu = sm.cur[s][c];
            pm = sm.pre[s][c];
        }
        bk4[s * 64 + c] = make_float4(sm.w1[c], cu, pm, 0.f);
        {   // momentum raw dots + w2 dots (cu=0 at step 0 gives exactly what's needed)
            float r0 = sm.mw[c] * cu + sm.mw[64 + c] * pm;
            float r1 = sm.mw[128 + c] * cu + sm.mw[192 + c] * pm;
            float r2 = sm.w2[c] * cu;
            float r3 = sm.w2[c] * pm;
            r0 = wredsum(r0); r1 = wredsum(r1); r2 = wredsum(r2); r3 = wredsum(r3);
            if (lane == 0) {
                float* rr = sm.red[s][half];
                rr[0] = r0; rr[1] = r1; rr[2] = r2; rr[3] = r3;
            }
        }
        if (t64 < 32) sm.pts[s][t64] = idx[(size_t)fc * KNB + t64] + boff;
        __syncthreads();
        if (t64 == 0) {
            float m0 = sm.red[s][0][0] + sm.red[s][1][0];
            float m1 = sm.red[s][0][1] + sm.red[s][1][1];
            sm.mm0[s] = m0; sm.mm1[s] = m1;
            g_mm[gi] = make_float2(m0, m1);
            sm.w2c[s] = sm.red[s][0][2] + sm.red[s][1][2];
            sm.w2p[s] = sm.red[s][0][3] + sm.red[s][1][3];
        }
        // gather 32 neighbor rows (float4 loads)
        {
            int kk = t64 >> 4, col = (t64 & 15) << 2;
#pragma unroll
            for (int k0 = 0; k0 < 8; k0++) {
                int k = k0 * 4 + kk;
                int pt = sm.pts[s][k];
                float4 v4 = __ldg((const float4*)&g_flat[((size_t)pt << 6) + col]);
                float* dst = &pv[(s * 32 + k) * 65 + col];
                dst[0] = v4.x; dst[1] = v4.y; dst[2] = v4.z; dst[3] = v4.w;
            }
        }
        __syncthreads();
        // merged per-k pass: L = w1.pv, P = cur.nb, R = pre.nb, N = |nb|^2 (nb elementwise)
        {
            int off = half * 32;
            const float* pvb = &pv[(s * 32 + lane) * 65 + off];
            const float4* bk = &bk4[s * 64 + off];
            float accL = 0.f, accP = 0.f, accR = 0.f, accN = 0.f;
#pragma unroll 8
            for (int cc = 0; cc < 32; cc++) {
                float v = pvb[cc];
                float4 q = bk[cc];
                accL += v * q.x;
                float nb = v - q.y;
                accP += q.y * nb;
                accR += q.z * nb;
                accN += nb * nb;
            }
            if (half == 1) {
                sm.hpart[s][0][lane] = accL;
                sm.hpart[s][1][lane] = accP;
                sm.hpart[s][2][lane] = accR;
                sm.hpart[s][3][lane] = accN;
            }
            __syncthreads();
            if (t64 < 32) {
                int k = lane;
                float L = accL + sm.hpart[s][0][k];
                sm.lpv[s][k] = L;
                sm.Pk[s][k] = accP + sm.hpart[s][1][k];
                sm.Rk[s][k] = accR + sm.hpart[s][2][k];
                sm.Nk[s][k] = accN + sm.hpart[s][3][k];
                float s1 = wredsum(L);
                float s2 = wredsum(L * L);
                if (k == 0) { sm.Lk[s] = s1; sm.Qk[s] = s2; }
            }
        }
        __syncthreads();
        // publish 6 momentum/agent partials (3 full warps, width-16 groups)
        if (t < 96) {
            int q = t >> 4, ss = t & 15;
            float m0 = sm.mm0[ss], m1 = sm.mm1[ss];
            double v = (q == 0) ? (double)m0 : (q == 1) ? (double)m1 :
                       (q == 2) ? (double)m0 * m0 : (q == 3) ? (double)m1 * m1 :
                       (q == 4) ? (double)sm.Lk[ss] : (double)sm.Qk[ss];
#pragma unroll
            for (int o = 8; o; o >>= 1) v += __shfl_xor_sync(0xffffffffu, v, o, 16);
            if ((t & 15) == 0) g_part[blockIdx.x][q] = v;
        }
        grid_bar();   // ================= bar 1 =================

        // ================= phase B: momentum BN + own gates + pre update (tiny) =================
        if (t < 192) {   // 6 full warps
            int w = t >> 5, ll = t & 31;
            double a = g_part[ll][w] + g_part[ll + 32][w]
                     + g_part[ll + 64][w] + g_part[ll + 96][w];
#pragma unroll
            for (int o = 16; o; o >>= 1) a += __shfl_xor_sync(0xffffffffu, a, o);
            if (ll == 0) sm.bns[w] = a;
        }
        __syncthreads();
        if (t == 0) {
            double m0 = sm.bns[0] * (1.0 / 2048.0), m1 = sm.bns[1] * (1.0 / 2048.0);
            double v0 = sm.bns[2] * (1.0 / 2048.0) - m0 * m0;
            double v1 = sm.bns[3] * (1.0 / 2048.0) - m1 * m1;
            sm.bnf[0] = (float)m0; sm.bnf[1] = (float)(1.0 / sqrt(v0 + 1e-5));
            sm.bnf[2] = (float)m1; sm.bnf[3] = (float)(1.0 / sqrt(v1 + 1e-5));
        }
        __syncthreads();
        if (t64 == 0) {
            float gaV, gbV;
            if (step == 0) { gaV = 0.f; gbV = 1.f; }
            else {
                gates_for(&g_mm[b << 8], j, sm.bnf[0], sm.bnf[1], sm.bnf[2], sm.bnf[3],
                          sm.mg0, sm.mg1, sm.mb0, sm.mb1, gaV, gbV);
            }
            sm.ga[s] = gaV; sm.gb[s] = gbV;
            sm.lpre[s] = gaV * sm.w2c[s] + gbV * sm.w2p[s];
        }
        __syncthreads();
        {
            float po = sm.pre[s][c];
            float pnew = (step == 0) ? po : (sm.ga[s] * cu + sm.gb[s] * po);
            sm.pre[s][c] = pnew;
            float ac = cu - pnew;
            float r0 = wredsum(ac * ac);
            if (lane == 0) sm.red[s][half][0] = r0;
        }
        __syncthreads();
        if (t64 == 0) sm.na[s] = sqrtf(sm.red[s][0][0] + sm.red[s][1][0]);
        // publish 3 lpre partials (2 FULL warps; q==3 is a dummy participant)
        if (t < 64) {
            int q = t >> 4, ss = t & 15;
            double v = 0.0;
            if (q < 3) {
                float lp = sm.lpre[ss];
                v = (q == 0) ? (double)lp : (q == 1) ? (double)lp * lp
                                          : (double)lp * sm.Lk[ss];
            }
#pragma unroll
            for (int o = 8; o; o >>= 1) v += __shfl_xor_sync(0xffffffffu, v, o, 16);
            if ((t & 15) == 0 && q < 3) g_part2[blockIdx.x][q] = v;
        }
        grid_bar();   // ================= bar 2 =================

        // ================= phase C: agent BN + crossover + select =================
        if (t < 96) {   // 3 full warps
            int w = t >> 5, ll = t & 31;
            double a = g_part2[ll][w] + g_part2[ll + 32][w]
                     + g_part2[ll + 64][w] + g_part2[ll + 96][w];
#pragma unroll
            for (int o = 16; o; o >>= 1) a += __shfl_xor_sync(0xffffffffu, a, o);
            if (ll == 0) sm.bns2[w] = a;
        }
        __syncthreads();
        if (t == 0) {
            double S  = sm.bns[4] + 32.0 * sm.bns2[0];
            double SS = sm.bns[5] + 2.0 * sm.bns2[2] + 32.0 * sm.bns2[1];
            double mean = S * (1.0 / 65536.0);
            double var  = SS * (1.0 / 65536.0) - mean * mean;
            sm.bnf[4] = (float)mean;
            sm.bnf[5] = (float)sqrt(var + 1e-5);
        }
        __syncthreads();
        if (t64 < 32) {
            int k = t64;
            float lg = sm.lpv[s][k] + sm.lpre[s];
            float z = (lg - sm.bnf[4]) / sm.bnf[5] * sm.ag + sm.ab;
            float l2 = z;
            if (step > 0) {
                float dotv = (1.f - sm.ga[s]) * sm.Pk[s][k] - sm.gb[s] * sm.Rk[s][k];
                float nbl = sqrtf(sm.Nk[s][k]);
                float dv = fmaxf(sm.na[s] * nbl, 1e-8f);
                float d = 1.f + dotv / dv;
                d = fminf(fmaxf(d, 0.f), 1.f);
                l2 = z * d;
            }
            float mx = l2;
#pragma unroll
            for (int o = 16; o; o >>= 1) mx = fmaxf(mx, __shfl_xor_sync(0xffffffffu, mx, o));
            float e = expf(l2 - mx);
            float se = wredsum(e);
            float y = e / se;
            unsigned long long key =
                ((unsigned long long)__float_as_uint(y) << 32) | (unsigned)(31 - k);
#pragma unroll
            for (int o = 16; o; o >>= 1) {
                unsigned long long kk = __shfl_xor_sync(0xffffffffu, key, o);
                if (kk > key) key = kk;
            }
            if (k == 0) {
                int sl = 31 - (int)(key & 0xFFFFFFFFull);
                sm.sel[s] = sl;
                sm.fcur[s] = sm.pts[s][sl];
            }
        }
        __syncthreads();
        {
            float nc = pv[(s * 32 + sm.sel[s]) * 65 + c];
            sm.cur[s][c] = nc;
            g_stage[((size_t)gi * CLEN + step) * 64 + c] = nc;
        }
        __syncthreads();
    }
}

// ----------------- K4: stage -> out transpose -----------------
__global__ void k_out(float* __restrict__ out) {
    __shared__ float tile[CLEN][65];
    int gi = blockIdx.x, b = gi >> 8, j = gi & 255;
    int t = threadIdx.x;   // 256
    for (int i = t; i < CLEN * 64; i += 256) {
        int st = i >> 6, c = i & 63;
        tile[st][c] = g_stage[((size_t)gi * CLEN + st) * 64 + c];
    }
    __syncthreads();
    for (int i = t; i < 64 * CLEN; i += 256) {
        int c = i >> 5, st = i & 31;
        out[((size_t)(b * 64 + c) * 256 + (size_t)j) * CLEN + st] = tile[st][c];
    }
}

// ----------------- launch -----------------
extern "C" void kernel_launch(void* const* d_in, const int* in_sizes, int n_in,
                              void* d_out, int out_size) {
    const float* x    = (const float*)d_in[0];
    // d_in[1] = xyz (unused by the reference forward)
    const int*   idx  = (const int*)d_in[2];
    const float* attw = (const float*)d_in[3];
    const float* agw  = (const float*)d_in[4];
    const float* agg  = (const float*)d_in[5];
    const float* agb  = (const float*)d_in[6];
    const float* mw   = (const float*)d_in[7];
    const float* mg   = (const float*)d_in[8];
    const float* mb   = (const float*)d_in[9];
    float* out = (float*)d_out;

    const int WALK_DYN = (16 * 32 * 65) * 4 + 16 * 64 * 16;   // pv + bk4
    cudaFuncSetAttribute(k_walk, cudaFuncAttributeMaxDynamicSharedMemorySize, WALK_DYN);

    k_prep<<<NB * 128, 256>>>(x, attw);
    k_topk<<<NB, 1024>>>();
    k_walk<<<PBLK, 1024, WALK_DYN>>>(idx, agw, agg, agb, mw, mg, mb);
    k_out<<<2048, 256>>>(out);
}

// round 12
// speedup vs baseline: 1.7728x; 1.1455x over previous
#include <cuda_runtime.h>
#include <cstdint>
#include <cstddef>

#define NB      8
#define NPTS    16384
#define KNB     32
#define CLEN    32
#define PBLK    128

// ----------------- global scratch -----------------
__device__ float  g_flat[(size_t)NB * NPTS * 64];   // point-major gated features
__device__ float  g_xatt[NB * NPTS];
__device__ int    g_start[2048];
__device__ float2 g_mm[2048];       // (m0,m1) per curve
__device__ double g_part[PBLK][4];  // bar1: m0,m1,m0^2,m1^2
__device__ double g_part2[PBLK][5]; // bar2: Lk,Qk,lp,lp^2,lp*Lk
__device__ float  g_stage[(size_t)2048 * CLEN * 64];
__device__ unsigned int g_barcnt;

__device__ __forceinline__ float wredsum(float v) {
#pragma unroll
    for (int o = 16; o; o >>= 1) v += __shfl_xor_sync(0xffffffffu, v, o);
    return v;
}

__device__ __forceinline__ void bar_arrive() {
    // caller guarantees a preceding __syncthreads so all block writes are done
    if (threadIdx.x == 0) {
        __threadfence();
        atomicAdd(&g_barcnt, 1u);
    }
}

__device__ __forceinline__ void bar_poll(unsigned target) {
    if (threadIdx.x == 0) {
        unsigned v;
        do {
            asm volatile("ld.global.acquire.gpu.u32 %0, [%1];" : "=r"(v) : "l"(&g_barcnt));
        } while (v < target);
    }
    __syncthreads();
}

// gate pair for curve (b,j) given that batch's raw momentum values
__device__ __forceinline__ void gates_for(const float2* mr, int jj,
                                          float mean0, float is0, float mean1, float is1,
                                          float mg0, float mg1, float mb0, float mb1,
                                          float& gaV, float& gbV) {
    int p0 = 2 * jj, p1 = p0 + 1;
    int q0 = p0 & 255, o0 = p0 >> 8, q1 = p1 & 255, o1 = p1 >> 8;
    float2 A = mr[q0];
    float z0 = (A.x - mean0) * is0 * mg0 + mb0;
    float z1 = (A.y - mean1) * is1 * mg1 + mb1;
    float mx = fmaxf(z0, z1);
    float e0 = expf(z0 - mx), e1 = expf(z1 - mx);
    gaV = ((o0 == 0) ? e0 : e1) / (e0 + e1);
    float2 B = mr[q1];
    z0 = (B.x - mean0) * is0 * mg0 + mb0;
    z1 = (B.y - mean1) * is1 * mg1 + mb1;
    mx = fmaxf(z0, z1);
    e0 = expf(z0 - mx); e1 = expf(z1 - mx);
    gbV = ((o1 == 0) ? e0 : e1) / (e0 + e1);
}

// ----------------- K1: gate + transpose -----------------
__global__ void __launch_bounds__(512, 4) k_prep(const float* __restrict__ x,
                                                 const float* __restrict__ attw) {
    __shared__ float sx[64][129];
    __shared__ float satt[128];
    __shared__ float swa[64];
    int t = threadIdx.x;                 // 512 threads
    int tile = blockIdx.x;               // 8 * 128
    int b = tile >> 7, p0 = (tile & 127) << 7;

    if (t < 64) swa[t] = attw[t];
    for (int i = t; i < 64 * 128; i += 512) {
        int c = i >> 7, p = i & 127;
        sx[c][p] = x[((size_t)(b * 64 + c) << 14) + p0 + p];
    }
    __syncthreads();
    if (t < 128) {
        float s = 0.f;
#pragma unroll
        for (int c = 0; c < 64; c++) s += sx[c][t] * swa[c];
        float a = 1.f / (1.f + expf(-s));
        satt[t] = a;
        g_xatt[((size_t)b << 14) + p0 + t] = a;
    }
    __syncthreads();
    for (int i = t; i < 128 * 64; i += 512) {
        int p = i >> 6, c = i & 63;
        g_flat[(((size_t)b << 14) + (size_t)(p0 + p)) * 64 + c] = sx[c][p] * satt[p];
    }
    if (tile == 0 && t == 0) g_barcnt = 0u;
}

// ----------------- K2: exact top-256 via histogram threshold + small bitonic -----------------
__global__ void __launch_bounds__(1024, 1) k_topk() {
    __shared__ int hist[2048];
    __shared__ unsigned long long cand[4096];
    __shared__ int csum[32];
    __shared__ int s_cnt, s_B;
    int b = blockIdx.x, t = threadIdx.x;
    int w = t >> 5, lane = t & 31;

    for (int i = t; i < 2048; i += 1024) hist[i] = 0;
    if (t == 0) s_cnt = 0;
    __syncthreads();
    for (int i = t; i < NPTS; i += 1024) {
        unsigned u = __float_as_uint(g_xatt[((size_t)b << 14) + i]);  // (0,1] positive
        atomicAdd(&hist[u >> 19], 1);
    }
    __syncthreads();
    {
        int acc = 0;
        for (int i = lane; i < 64; i += 32) acc += hist[w * 64 + i];
#pragma unroll
        for (int o = 16; o; o >>= 1) acc += __shfl_xor_sync(0xffffffffu, acc, o);
        if (lane == 0) csum[w] = acc;
    }
    __syncthreads();
    if (t == 0) {
        int accum = 0, wsel = 0;
        for (int ww = 31; ww >= 0; ww--) {
            if (accum + csum[ww] >= 256) { wsel = ww; break; }
            accum += csum[ww];
        }
        int B = wsel * 64;
        for (int bkt = wsel * 64 + 63; bkt >= wsel * 64; bkt--) {
            accum += hist[bkt];
            if (accum >= 256) { B = bkt; break; }
        }
        s_B = B;
    }
    __syncthreads();
    int B = s_B;
    for (int i = t; i < NPTS; i += 1024) {
        unsigned u = __float_as_uint(g_xatt[((size_t)b << 14) + i]);
        if ((int)(u >> 19) >= B) {
            int p = atomicAdd(&s_cnt, 1);
            if (p < 4096)
                cand[p] = ((unsigned long long)u << 32) | (unsigned)(0xFFFFFFFFu - (unsigned)i);
        }
    }
    __syncthreads();
    int n = s_cnt; if (n > 4096) n = 4096;
    for (int i = t; i < 4096; i += 1024)
        if (i >= n) cand[i] = 0ull;
    for (int size = 2; size <= 4096; size <<= 1) {
        for (int stride = size >> 1; stride > 0; stride >>= 1) {
            __syncthreads();
            for (int i = t; i < 2048; i += 1024) {
                int pos = 2 * i - (i & (stride - 1));
                unsigned long long a = cand[pos], bb = cand[pos + stride];
                bool asc = (pos & size) != 0;
                bool sw = asc ? (a > bb) : (a < bb);
                if (sw) { cand[pos] = bb; cand[pos + stride] = a; }
            }
        }
    }
    __syncthreads();
    if (t < 256) {
        unsigned low = (unsigned)(cand[t] & 0xFFFFFFFFull);
        int p = (int)(0xFFFFFFFFu - low);
        g_start[(b << 8) + t] = (b << 14) + p;
    }
}

// ----------------- K3: persistent curve walk, split arrive/poll barriers -----------------
struct SW {
    float  cur[16][64], pre[16][64];
    float  w1[64], w2[64], mw[256];
    float  lpv[16][32], Pk[16][32], Rk[16][32], Nk[16][32];
    int    pts[16][32];
    float  hpart[16][4][32];
    float  red[16][2][4];
    float  mm0[16], mm1[16], w2c[16], w2p[16];
    float  lpre[16], na[16], ga[16], gb[16];
    float  Lk[16], Qk[16];
    int    fcur[16], sel[16];
    float  ag, ab, mg0, mg1, mb0, mb1;
    float  bnf[6];
    double bns[4], bns2[5];
};

__global__ void __launch_bounds__(1024, 1) k_walk(
    const int* __restrict__ idx,
    const float* __restrict__ agw, const float* __restrict__ agg, const float* __restrict__ agb,
    const float* __restrict__ mwi, const float* __restrict__ mgi, const float* __restrict__ mbi)
{
    __shared__ SW sm;
    extern __shared__ float dyn[];
    float*  pv  = dyn;                                  // [16][32][65]
    float4* bk4 = (float4*)(dyn + 16 * 32 * 65);        // [16][64] (w1,cur,pre,-)

    int t = threadIdx.x;
    int s = t >> 6, t64 = t & 63, half = t64 >> 5, lane = t & 31, c = t64;
    int gi = (blockIdx.x << 4) + s;
    int b = gi >> 8, j = gi & 255, boff = b << 14;
    unsigned epoch = 1;

    if (t < 64) { sm.w1[t] = agw[t]; sm.w2[t] = agw[64 + t]; }
    if (t >= 256 && t < 512) sm.mw[t - 256] = mwi[t - 256];
    if (t == 0) {
        sm.ag = agg[0]; sm.ab = agb[0];
        sm.mg0 = mgi[0]; sm.mg1 = mgi[1]; sm.mb0 = mbi[0]; sm.mb1 = mbi[1];
    }
    if (t64 == 0) sm.fcur[s] = g_start[gi];
    __syncthreads();

    for (int step = 0; step < CLEN; step++) {
        // ===== segment 1: dots + gather, then publish + ARRIVE bar1 =====
        int fc = sm.fcur[s];
        float cu, pm;
        if (step == 0) {
            pm = g_flat[((size_t)fc << 6) + c];
            cu = 0.f;
            sm.cur[s][c] = 0.f;
            sm.pre[s][c] = pm;
        } else {
            cu = sm.cur[s][c];
            pm = sm.pre[s][c];
        }
        bk4[s * 64 + c] = make_float4(sm.w1[c], cu, pm, 0.f);
        {   // momentum raw dots + w2 dots
            float r0 = sm.mw[c] * cu + sm.mw[64 + c] * pm;
            float r1 = sm.mw[128 + c] * cu + sm.mw[192 + c] * pm;
            float r2 = sm.w2[c] * cu;
            float r3 = sm.w2[c] * pm;
            r0 = wredsum(r0); r1 = wredsum(r1); r2 = wredsum(r2); r3 = wredsum(r3);
            if (lane == 0) {
                float* rr = sm.red[s][half];
                rr[0] = r0; rr[1] = r1; rr[2] = r2; rr[3] = r3;
            }
        }
        if (t64 < 32) sm.pts[s][t64] = idx[(size_t)fc * KNB + t64] + boff;
        __syncthreads();   // S1
        if (t64 == 0) {
            float m0 = sm.red[s][0][0] + sm.red[s][1][0];
            float m1 = sm.red[s][0][1] + sm.red[s][1][1];
            sm.mm0[s] = m0; sm.mm1[s] = m1;
            g_mm[gi] = make_float2(m0, m1);
            sm.w2c[s] = sm.red[s][0][2] + sm.red[s][1][2];
            sm.w2p[s] = sm.red[s][0][3] + sm.red[s][1][3];
        }
        // gather 32 neighbor rows (float4 loads)
        {
            int kk = t64 >> 4, col = (t64 & 15) << 2;
#pragma unroll
            for (int k0 = 0; k0 < 8; k0++) {
                int k = k0 * 4 + kk;
                int pt = sm.pts[s][k];
                float4 v4 = __ldg((const float4*)&g_flat[((size_t)pt << 6) + col]);
                float* dst = &pv[(s * 32 + k) * 65 + col];
                dst[0] = v4.x; dst[1] = v4.y; dst[2] = v4.z; dst[3] = v4.w;
            }
        }
        __syncthreads();   // S2 (mm0/g_mm + pv visible)
        // publish bar1 partials: m0, m1, m0^2, m1^2 (2 full warps)
        if (t < 64) {
            int q = t >> 4, ss = t & 15;
            float m0 = sm.mm0[ss], m1 = sm.mm1[ss];
            double v = (q == 0) ? (double)m0 : (q == 1) ? (double)m1 :
                       (q == 2) ? (double)m0 * m0 : (double)m1 * m1;
#pragma unroll
            for (int o = 8; o; o >>= 1) v += __shfl_xor_sync(0xffffffffu, v, o, 16);
            if ((t & 15) == 0) g_part[blockIdx.x][q] = v;
        }
        __syncthreads();   // S3 (publish + g_mm visible before arrival)
        bar_arrive();      // ===== arrive bar1 =====

        // ===== heavy per-k pass, overlapped with bar1 skew =====
        {
            int off = half * 32;
            const float* pvb = &pv[(s * 32 + lane) * 65 + off];
            const float4* bk = &bk4[s * 64 + off];
            float accL = 0.f, accP = 0.f, accR = 0.f, accN = 0.f;
#pragma unroll 8
            for (int cc = 0; cc < 32; cc++) {
                float v = pvb[cc];
                float4 q = bk[cc];
                accL += v * q.x;
                float nb = v - q.y;
                accP += q.y * nb;
                accR += q.z * nb;
                accN += nb * nb;
            }
            if (half == 1) {
                sm.hpart[s][0][lane] = accL;
                sm.hpart[s][1][lane] = accP;
                sm.hpart[s][2][lane] = accR;
                sm.hpart[s][3][lane] = accN;
            }
            __syncthreads();   // S4
            if (t64 < 32) {
                int k = lane;
                float L = accL + sm.hpart[s][0][k];
                sm.lpv[s][k] = L;
                sm.Pk[s][k] = accP + sm.hpart[s][1][k];
                sm.Rk[s][k] = accR + sm.hpart[s][2][k];
                sm.Nk[s][k] = accN + sm.hpart[s][3][k];
                float s1 = wredsum(L);
                float s2 = wredsum(L * L);
                if (k == 0) { sm.Lk[s] = s1; sm.Qk[s] = s2; }
            }
        }
        __syncthreads();   // S5
        bar_poll(PBLK * epoch); epoch++;   // ===== poll bar1 (incl. trailing sync) =====

        // ===== BN1: momentum BN + gates + lpre, publish + ARRIVE bar2 =====
        if (t < 128) {   // 4 full warps
            int w = t >> 5, ll = t & 31;
            double a = g_part[ll][w] + g_part[ll + 32][w]
                     + g_part[ll + 64][w] + g_part[ll + 96][w];
#pragma unroll
            for (int o = 16; o; o >>= 1) a += __shfl_xor_sync(0xffffffffu, a, o);
            if (ll == 0) sm.bns[w] = a;
        }
        __syncthreads();   // S6
        if (t == 0) {
            double m0 = sm.bns[0] * (1.0 / 2048.0), m1 = sm.bns[1] * (1.0 / 2048.0);
            double v0 = sm.bns[2] * (1.0 / 2048.0) - m0 * m0;
            double v1 = sm.bns[3] * (1.0 / 2048.0) - m1 * m1;
            sm.bnf[0] = (float)m0; sm.bnf[1] = (float)(1.0 / sqrt(v0 + 1e-5));
            sm.bnf[2] = (float)m1; sm.bnf[3] = (float)(1.0 / sqrt(v1 + 1e-5));
        }
        __syncthreads();   // S7
        if (t64 == 0) {
            float gaV, gbV;
            if (step == 0) { gaV = 0.f; gbV = 1.f; }
            else {
                gates_for(&g_mm[b << 8], j, sm.bnf[0], sm.bnf[1], sm.bnf[2], sm.bnf[3],
                          sm.mg0, sm.mg1, sm.mb0, sm.mb1, gaV, gbV);
            }
            sm.ga[s] = gaV; sm.gb[s] = gbV;
            sm.lpre[s] = gaV * sm.w2c[s] + gbV * sm.w2p[s];
        }
        __syncthreads();   // S8
        // publish bar2 partials: Lk, Qk, lp, lp^2, lp*Lk (3 full warps, q==5 dummy)
        if (t < 96) {
            int q = t >> 4, ss = t & 15;
            double v = 0.0;
            if (q < 5) {
                float lp = sm.lpre[ss];
                v = (q == 0) ? (double)sm.Lk[ss] : (q == 1) ? (double)sm.Qk[ss] :
                    (q == 2) ? (double)lp : (q == 3) ? (double)lp * lp
                                          : (double)lp * sm.Lk[ss];
            }
#pragma unroll
            for (int o = 8; o; o >>= 1) v += __shfl_xor_sync(0xffffffffu, v, o, 16);
            if ((t & 15) == 0 && q < 5) g_part2[blockIdx.x][q] = v;
        }
        __syncthreads();   // S9
        bar_arrive();      // ===== arrive bar2 =====

        // ===== pre update + na, overlapped with bar2 skew =====
        {
            float po = sm.pre[s][c];
            float pnew = sm.ga[s] * cu + sm.gb[s] * po;
            sm.pre[s][c] = pnew;
            float ac = cu - pnew;
            float r0 = wredsum(ac * ac);
            if (lane == 0) sm.red[s][half][0] = r0;
        }
        __syncthreads();   // S10
        if (t64 == 0) sm.na[s] = sqrtf(sm.red[s][0][0] + sm.red[s][1][0]);
        bar_poll(PBLK * epoch); epoch++;   // ===== poll bar2 (incl. trailing sync) =====

        // ===== BN2: agent BN + crossover + select =====
        if (t < 160) {   // 5 full warps
            int w = t >> 5, ll = t & 31;
            double a = g_part2[ll][w] + g_part2[ll + 32][w]
                     + g_part2[ll + 64][w] + g_part2[ll + 96][w];
#pragma unroll
            for (int o = 16; o; o >>= 1) a += __shfl_xor_sync(0xffffffffu, a, o);
            if (ll == 0) sm.bns2[w] = a;
        }
        __syncthreads();   // S11
        if (t == 0) {
            double S  = sm.bns2[0] + 32.0 * sm.bns2[2];
            double SS = sm.bns2[1] + 2.0 * sm.bns2[4] + 32.0 * sm.bns2[3];
            double mean = S * (1.0 / 65536.0);
            double var  = SS * (1.0 / 65536.0) - mean * mean;
            sm.bnf[4] = (float)mean;
            sm.bnf[5] = (float)sqrt(var + 1e-5);
        }
        __syncthreads();   // S12
        if (t64 < 32) {
            int k = t64;
            float lg = sm.lpv[s][k] + sm.lpre[s];
            float z = (lg - sm.bnf[4]) / sm.bnf[5] * sm.ag + sm.ab;
            float l2 = z;
            if (step > 0) {
                float dotv = (1.f - sm.ga[s]) * sm.Pk[s][k] - sm.gb[s] * sm.Rk[s][k];
                float nbl = sqrtf(sm.Nk[s][k]);
                float dv = fmaxf(sm.na[s] * nbl, 1e-8f);
                float d = 1.f + dotv / dv;
                d = fminf(fmaxf(d, 0.f), 1.f);
                l2 = z * d;
            }
            float mx = l2;
#pragma unroll
            for (int o = 16; o; o >>= 1) mx = fmaxf(mx, __shfl_xor_sync(0xffffffffu, mx, o));
            float e = expf(l2 - mx);
            float se = wredsum(e);
            float y = e / se;
            unsigned long long key =
                ((unsigned long long)__float_as_uint(y) << 32) | (unsigned)(31 - k);
#pragma unroll
            for (int o = 16; o; o >>= 1) {
                unsigned long long kk = __shfl_xor_sync(0xffffffffu, key, o);
                if (kk > key) key = kk;
            }
            if (k == 0) {
                int sl = 31 - (int)(key & 0xFFFFFFFFull);
                sm.sel[s] = sl;
                sm.fcur[s] = sm.pts[s][sl];
            }
        }
        __syncthreads();   // S13
        {
            float nc = pv[(s * 32 + sm.sel[s]) * 65 + c];
            sm.cur[s][c] = nc;
            g_stage[((size_t)gi * CLEN + step) * 64 + c] = nc;
        }
        // pv reads complete before S1 of next iteration gates the next gather
    }
}

// ----------------- K4: stage -> out transpose -----------------
__global__ void k_out(float* __restrict__ out) {
    __shared__ float tile[CLEN][65];
    int gi = blockIdx.x, b = gi >> 8, j = gi & 255;
    int t = threadIdx.x;   // 256
    for (int i = t; i < CLEN * 64; i += 256) {
        int st = i >> 6, c = i & 63;
        tile[st][c] = g_stage[((size_t)gi * CLEN + st) * 64 + c];
    }
    __syncthreads();
    for (int i = t; i < 64 * CLEN; i += 256) {
        int c = i >> 5, st = i & 31;
        out[((size_t)(b * 64 + c) * 256 + (size_t)j) * CLEN + st] = tile[st][c];
    }
}

// ----------------- launch -----------------
extern "C" void kernel_launch(void* const* d_in, const int* in_sizes, int n_in,
                              void* d_out, int out_size) {
    const float* x    = (const float*)d_in[0];
    // d_in[1] = xyz (unused by the reference forward)
    const int*   idx  = (const int*)d_in[2];
    const float* attw = (const float*)d_in[3];
    const float* agw  = (const float*)d_in[4];
    const float* agg  = (const float*)d_in[5];
    const float* agb  = (const float*)d_in[6];
    const float* mw   = (const float*)d_in[7];
    const float* mg   = (const float*)d_in[8];
    const float* mb   = (const float*)d_in[9];
    float* out = (float*)d_out;

    const int WALK_DYN = (16 * 32 * 65) * 4 + 16 * 64 * 16;   // pv + bk4
    cudaFuncSetAttribute(k_walk, cudaFuncAttributeMaxDynamicSharedMemorySize, WALK_DYN);

    k_prep<<<NB * 128, 512>>>(x, attw);
    k_topk<<<NB, 1024>>>();
    k_walk<<<PBLK, 1024, WALK_DYN>>>(idx, agw, agg, agb, mw, mg, mb);
    k_out<<<2048, 256>>>(out);
}